// round 12
// baseline (speedup 1.0000x reference)
#include <cuda_runtime.h>
#include <cuda_bf16.h>
#include <stdint.h>
#include <math.h>

typedef unsigned int u32;
typedef unsigned long long u64;

// Problem constants
constexpr int B_   = 2;
constexpr int S_   = 2048;
constexpr int HID_ = 1024;
constexpr int NH_  = 16;
constexpr int DK_  = 64;
constexpr int M_   = B_ * S_;   // 4096

// ---------------------------------------------------------------------------
// Scratch (device globals; no allocation allowed)
// ---------------------------------------------------------------------------
__device__ float g_q  [B_ * NH_ * S_ * DK_];
__device__ float g_k  [B_ * NH_ * S_ * DK_];
__device__ float g_v  [B_ * NH_ * S_ * DK_];
__device__ float g_att[B_ * S_ * HID_];

// ---------------------------------------------------------------------------
// f32x2 packed helpers
// ---------------------------------------------------------------------------
__device__ __forceinline__ void fma2(u64& d, u64 a, u64 b) {
    asm("fma.rn.f32x2 %0, %1, %2, %0;" : "+l"(d) : "l"(a), "l"(b));
}
__device__ __forceinline__ float2 upk2(u64 v) {
    u32 lo, hi;
    asm("mov.b64 {%0, %1}, %2;" : "=r"(lo), "=r"(hi) : "l"(v));
    return make_float2(__uint_as_float(lo), __uint_as_float(hi));
}

// ---------------------------------------------------------------------------
// FFMA2 SGEMM (M-pair packed): C = A @ W^T + bias
// A [M,1024] row-major, W [N,1024] row-major.
// CTA tile 256m x 128n, k-tile 16, 256 threads (tx 0..15 n, ty 0..15 m).
// Per thread: 8 m-pairs (m = ty*16 + 2*ip) x 8 n (n = tx*8 + j).
// As2 staged transposed [k][m] (m-pairs -> u64 loads).
// Ws2 staged duplicated [k][2n] (dup pairs -> u64 loads).
// MODE 0: C row-major [M,1024];  MODE 1: C in [B,NH,S,DK] layout.
// SCALEA: scale A rows by (1 + abias[row]) during staging.
// ---------------------------------------------------------------------------
constexpr int P2_LD = 260;                       // smem row stride (floats)
constexpr int P2_SMEM = 2 * 16 * P2_LD * 4;      // 33280 bytes

template <int MODE, int SCALEA>
__global__ __launch_bounds__(256)
void sgemm2p(const float* __restrict__ A, const float* __restrict__ W,
             const float* __restrict__ bias, const float* __restrict__ abias,
             float* __restrict__ C) {
    extern __shared__ float smf[];
    float* As2 = smf;                  // [16][260] (m-transposed)
    float* Ws2 = smf + 16 * P2_LD;     // [16][260] (n duplicated)

    const int tid = threadIdx.x;
    const int tx  = tid & 15;
    const int ty  = tid >> 4;
    const int m0  = blockIdx.y * 256;
    const int n0  = blockIdx.x * 128;

    u64 acc2[8][8];
#pragma unroll
    for (int ip = 0; ip < 8; ip++)
#pragma unroll
        for (int j = 0; j < 8; j++) acc2[ip][j] = 0ull;

    const int c4 = tid & 3;        // which float4 of the 16-wide k-tile
    const int rA = tid >> 2;       // 0..63 (A row within group of 64)
    const int rW = tid >> 2;       // 0..63 (W row)

    for (int kt = 0; kt < 64; kt++) {
        const int k0 = kt * 16;

        // global loads first (overlap with nothing but keeps pattern simple)
        float4 ga[4];
        float  fs[4];
#pragma unroll
        for (int it = 0; it < 4; it++) {
            int r = rA + it * 64;
            ga[it] = *(const float4*)&A[(size_t)(m0 + r) * 1024 + k0 + c4 * 4];
            if (SCALEA) fs[it] = 1.0f + abias[m0 + r];
        }
        float4 gw[2];
#pragma unroll
        for (int it = 0; it < 2; it++) {
            int r = rW + it * 64;
            gw[it] = *(const float4*)&W[(size_t)(n0 + r) * 1024 + k0 + c4 * 4];
        }

        __syncthreads();
        // scatter A transposed: As2[kk][m]
#pragma unroll
        for (int it = 0; it < 4; it++) {
            int r = rA + it * 64;
            float4 a = ga[it];
            if (SCALEA) { a.x *= fs[it]; a.y *= fs[it]; a.z *= fs[it]; a.w *= fs[it]; }
            As2[(c4 * 4 + 0) * P2_LD + r] = a.x;
            As2[(c4 * 4 + 1) * P2_LD + r] = a.y;
            As2[(c4 * 4 + 2) * P2_LD + r] = a.z;
            As2[(c4 * 4 + 3) * P2_LD + r] = a.w;
        }
        // scatter W transposed + duplicated: Ws2[kk][2n], [2n+1]
#pragma unroll
        for (int it = 0; it < 2; it++) {
            int r = rW + it * 64;
            float4 w = gw[it];
            *(float2*)&Ws2[(c4 * 4 + 0) * P2_LD + 2 * r] = make_float2(w.x, w.x);
            *(float2*)&Ws2[(c4 * 4 + 1) * P2_LD + 2 * r] = make_float2(w.y, w.y);
            *(float2*)&Ws2[(c4 * 4 + 2) * P2_LD + 2 * r] = make_float2(w.z, w.z);
            *(float2*)&Ws2[(c4 * 4 + 3) * P2_LD + 2 * r] = make_float2(w.w, w.w);
        }
        __syncthreads();

#pragma unroll
        for (int kk = 0; kk < 16; kk++) {
            const float* arow = &As2[kk * P2_LD + ty * 16];
            const float* brow = &Ws2[kk * P2_LD + tx * 16];
            ulonglong2 aq0 = *(const ulonglong2*)(arow + 0);
            ulonglong2 aq1 = *(const ulonglong2*)(arow + 4);
            ulonglong2 aq2 = *(const ulonglong2*)(arow + 8);
            ulonglong2 aq3 = *(const ulonglong2*)(arow + 12);
            ulonglong2 bq0 = *(const ulonglong2*)(brow + 0);
            ulonglong2 bq1 = *(const ulonglong2*)(brow + 4);
            ulonglong2 bq2 = *(const ulonglong2*)(brow + 8);
            ulonglong2 bq3 = *(const ulonglong2*)(brow + 12);
            u64 a2[8] = {aq0.x, aq0.y, aq1.x, aq1.y, aq2.x, aq2.y, aq3.x, aq3.y};
            u64 b2[8] = {bq0.x, bq0.y, bq1.x, bq1.y, bq2.x, bq2.y, bq3.x, bq3.y};
#pragma unroll
            for (int ip = 0; ip < 8; ip++)
#pragma unroll
                for (int j = 0; j < 8; j++)
                    fma2(acc2[ip][j], a2[ip], b2[j]);
        }
    }

    // epilogue
#pragma unroll
    for (int ip = 0; ip < 8; ip++) {
        const int m = m0 + ty * 16 + 2 * ip;     // even row; odd = m+1
        float4 lo0, lo1, hi0, hi1;
        float2 p;
        p = upk2(acc2[ip][0]); lo0.x = p.x; hi0.x = p.y;
        p = upk2(acc2[ip][1]); lo0.y = p.x; hi0.y = p.y;
        p = upk2(acc2[ip][2]); lo0.z = p.x; hi0.z = p.y;
        p = upk2(acc2[ip][3]); lo0.w = p.x; hi0.w = p.y;
        p = upk2(acc2[ip][4]); lo1.x = p.x; hi1.x = p.y;
        p = upk2(acc2[ip][5]); lo1.y = p.x; hi1.y = p.y;
        p = upk2(acc2[ip][6]); lo1.z = p.x; hi1.z = p.y;
        p = upk2(acc2[ip][7]); lo1.w = p.x; hi1.w = p.y;
        const int n = n0 + tx * 8;
        float4 bv0 = *(const float4*)&bias[n];
        float4 bv1 = *(const float4*)&bias[n + 4];
        lo0.x += bv0.x; lo0.y += bv0.y; lo0.z += bv0.z; lo0.w += bv0.w;
        hi0.x += bv0.x; hi0.y += bv0.y; hi0.z += bv0.z; hi0.w += bv0.w;
        lo1.x += bv1.x; lo1.y += bv1.y; lo1.z += bv1.z; lo1.w += bv1.w;
        hi1.x += bv1.x; hi1.y += bv1.y; hi1.z += bv1.z; hi1.w += bv1.w;
        if (MODE == 0) {
            *(float4*)&C[(size_t)m * 1024 + n]           = lo0;
            *(float4*)&C[(size_t)m * 1024 + n + 4]       = lo1;
            *(float4*)&C[(size_t)(m + 1) * 1024 + n]     = hi0;
            *(float4*)&C[(size_t)(m + 1) * 1024 + n + 4] = hi1;
        } else {
            const int h = n >> 6;
            const int d = n & 63;
            const int bb0 = m >> 11, ss0 = m & (S_ - 1);
            const int bb1 = (m + 1) >> 11, ss1 = (m + 1) & (S_ - 1);
            size_t base0 = ((size_t)(bb0 * NH_ + h) * S_ + ss0) * DK_ + d;
            size_t base1 = ((size_t)(bb1 * NH_ + h) * S_ + ss1) * DK_ + d;
            *(float4*)&C[base0]     = lo0;
            *(float4*)&C[base0 + 4] = lo1;
            *(float4*)&C[base1]     = hi0;
            *(float4*)&C[base1 + 4] = hi1;
        }
    }
}

// ---------------------------------------------------------------------------
// Fused flash attention (R10 proven version, byte-identical)
// ---------------------------------------------------------------------------
constexpr int FLASH_SMEM = (16576 + 64) * 4;   // 66560 bytes

__global__ __launch_bounds__(256)
void flash_kernel(const float* __restrict__ Q, const float* __restrict__ K,
                  const float* __restrict__ V, const int* __restrict__ mask,
                  float* __restrict__ out) {
    extern __shared__ float sm[];
    float* Qs    = sm;            // [d][q]
    float* Ks    = sm + 4096;     // [d][k]
    float* Vs    = sm + 8192;     // [k][d]
    float* ST    = sm + 12288;    // [k][q], stride 65
    float* alf   = sm + 16448;
    float* linv  = sm + 16512;
    int*   msk   = (int*)(sm + 16576);

    const int tid = threadIdx.x;
    const int tx  = tid & 15;
    const int ty  = tid >> 4;
    const int b   = blockIdx.z;
    const int h   = blockIdx.y;
    const int q0  = blockIdx.x * 64;
    const int bh  = b * NH_ + h;

    const float* Qb = Q + (size_t)bh * S_ * DK_;
    const float* Kb = K + (size_t)bh * S_ * DK_;
    const float* Vb = V + (size_t)bh * S_ * DK_;
    const int*   mb = mask + b * S_;

#pragma unroll
    for (int i = 0; i < 4; i++) {
        int f = tid + i * 256;
        int r = f >> 4;
        int c = (f & 15) * 4;
        float4 qv = *(const float4*)(Qb + (size_t)(q0 + r) * DK_ + c);
        Qs[(c + 0) * 64 + r] = qv.x;
        Qs[(c + 1) * 64 + r] = qv.y;
        Qs[(c + 2) * 64 + r] = qv.z;
        Qs[(c + 3) * 64 + r] = qv.w;
    }

    float Ob[4][4];
#pragma unroll
    for (int i = 0; i < 4; i++)
#pragma unroll
        for (int j = 0; j < 4; j++) Ob[i][j] = 0.0f;

    const int r    = ty * 4 + (tx & 3);
    const int k0s  = (tx >> 2) * 16;
    float m_row = -1.0e30f;
    float l_row = 0.0f;

    for (int kt = 0; kt < S_; kt += 64) {
        __syncthreads();

#pragma unroll
        for (int i = 0; i < 4; i++) {
            int f = tid + i * 256;
            int rr = f >> 4;
            int cc = (f & 15) * 4;
            float4 kv = *(const float4*)(Kb + (size_t)(kt + rr) * DK_ + cc);
            Ks[(cc + 0) * 64 + rr] = kv.x;
            Ks[(cc + 1) * 64 + rr] = kv.y;
            Ks[(cc + 2) * 64 + rr] = kv.z;
            Ks[(cc + 3) * 64 + rr] = kv.w;
            float4 vv = *(const float4*)(Vb + (size_t)(kt + rr) * DK_ + cc);
            *(float4*)&Vs[rr * 64 + cc] = vv;
        }
        if (tid < 64) msk[tid] = mb[kt + tid];
        __syncthreads();

        float sacc[4][4];
#pragma unroll
        for (int i = 0; i < 4; i++)
#pragma unroll
            for (int j = 0; j < 4; j++) sacc[i][j] = 0.0f;

#pragma unroll 8
        for (int d = 0; d < DK_; d++) {
            float4 a  = *(const float4*)&Qs[d * 64 + ty * 4];
            float4 bb = *(const float4*)&Ks[d * 64 + tx * 4];
            float af[4] = {a.x, a.y, a.z, a.w};
            float bf[4] = {bb.x, bb.y, bb.z, bb.w};
#pragma unroll
            for (int i = 0; i < 4; i++)
#pragma unroll
                for (int j = 0; j < 4; j++) sacc[i][j] += af[i] * bf[j];
        }

#pragma unroll
        for (int j = 0; j < 4; j++) {
            const int mk = msk[tx * 4 + j];
#pragma unroll
            for (int i = 0; i < 4; i++) {
                ST[(tx * 4 + j) * 65 + ty * 4 + i] =
                    mk ? sacc[i][j] * 0.125f : -10000.0f;
            }
        }
        __syncthreads();

        float tm = -1.0e30f;
#pragma unroll
        for (int t = 0; t < 16; t++)
            tm = fmaxf(tm, ST[(k0s + t) * 65 + r]);
        tm = fmaxf(tm, __shfl_xor_sync(0xFFFFFFFFu, tm, 4));
        tm = fmaxf(tm, __shfl_xor_sync(0xFFFFFFFFu, tm, 8));

        const float m_new = fmaxf(m_row, tm);
        const float al    = __expf(m_row - m_new);
        float sum = 0.0f;
#pragma unroll
        for (int t = 0; t < 16; t++) {
            float e = __expf(ST[(k0s + t) * 65 + r] - m_new);
            ST[(k0s + t) * 65 + r] = e;
            sum += e;
        }
        sum += __shfl_xor_sync(0xFFFFFFFFu, sum, 4);
        sum += __shfl_xor_sync(0xFFFFFFFFu, sum, 8);
        l_row = l_row * al + sum;
        m_row = m_new;
        if ((tx >> 2) == 0) alf[r] = al;
        __syncthreads();

        float a0 = alf[ty * 4 + 0];
        float a1 = alf[ty * 4 + 1];
        float a2 = alf[ty * 4 + 2];
        float a3 = alf[ty * 4 + 3];
#pragma unroll
        for (int j = 0; j < 4; j++) {
            Ob[0][j] *= a0; Ob[1][j] *= a1; Ob[2][j] *= a2; Ob[3][j] *= a3;
        }

#pragma unroll 4
        for (int kk = 0; kk < 64; kk++) {
            float p0 = ST[kk * 65 + ty * 4 + 0];
            float p1 = ST[kk * 65 + ty * 4 + 1];
            float p2 = ST[kk * 65 + ty * 4 + 2];
            float p3 = ST[kk * 65 + ty * 4 + 3];
            float4 bv = *(const float4*)&Vs[kk * 64 + tx * 4];
            float bf[4] = {bv.x, bv.y, bv.z, bv.w};
#pragma unroll
            for (int j = 0; j < 4; j++) {
                Ob[0][j] += p0 * bf[j];
                Ob[1][j] += p1 * bf[j];
                Ob[2][j] += p2 * bf[j];
                Ob[3][j] += p3 * bf[j];
            }
        }
    }

    if ((tx >> 2) == 0) linv[r] = 1.0f / l_row;
    __syncthreads();

#pragma unroll
    for (int i = 0; i < 4; i++) {
        const float rv = linv[ty * 4 + i];
        float4 o;
        o.x = Ob[i][0] * rv; o.y = Ob[i][1] * rv;
        o.z = Ob[i][2] * rv; o.w = Ob[i][3] * rv;
        *(float4*)(out + ((size_t)b * S_ + q0 + ty * 4 + i) * HID_ + h * DK_ + tx * 4) = o;
    }
}

// ---------------------------------------------------------------------------
// launch
// ---------------------------------------------------------------------------
extern "C" void kernel_launch(void* const* d_in, const int* in_sizes, int n_in,
                              void* d_out, int out_size) {
    const float* query = (const float*)d_in[0];
    const float* key   = (const float*)d_in[1];
    const float* value = (const float*)d_in[2];
    const float* bias  = (const float*)d_in[3];
    const int*   mask  = (const int*)  d_in[4];
    const float* wq    = (const float*)d_in[5];
    const float* bq    = (const float*)d_in[6];
    const float* wk    = (const float*)d_in[7];
    const float* bk    = (const float*)d_in[8];
    const float* wv    = (const float*)d_in[9];
    const float* bv    = (const float*)d_in[10];
    const float* wo    = (const float*)d_in[11];
    const float* bo    = (const float*)d_in[12];
    float* out = (float*)d_out;

    float *p_q, *p_k, *p_v, *p_att;
    cudaGetSymbolAddress((void**)&p_q,   g_q);
    cudaGetSymbolAddress((void**)&p_k,   g_k);
    cudaGetSymbolAddress((void**)&p_v,   g_v);
    cudaGetSymbolAddress((void**)&p_att, g_att);

    cudaFuncSetAttribute(sgemm2p<0, 0>, cudaFuncAttributeMaxDynamicSharedMemorySize, P2_SMEM);
    cudaFuncSetAttribute(sgemm2p<1, 0>, cudaFuncAttributeMaxDynamicSharedMemorySize, P2_SMEM);
    cudaFuncSetAttribute(sgemm2p<1, 1>, cudaFuncAttributeMaxDynamicSharedMemorySize, P2_SMEM);
    cudaFuncSetAttribute(flash_kernel,  cudaFuncAttributeMaxDynamicSharedMemorySize, FLASH_SMEM);

    dim3 ggrid(1024 / 128, M_ / 256);    // (8, 16) = 128 CTAs

    // 1) projections (K/V scaled by 1+bias during staging), write [B,NH,S,DK]
    sgemm2p<1, 0><<<ggrid, 256, P2_SMEM>>>(query, wq, bq, nullptr, p_q);
    sgemm2p<1, 1><<<ggrid, 256, P2_SMEM>>>(key,   wk, bk, bias,    p_k);
    sgemm2p<1, 1><<<ggrid, 256, P2_SMEM>>>(value, wv, bv, bias,    p_v);

    // 2) fused flash attention
    {
        dim3 grid(S_ / 64, NH_, B_);     // (32, 16, 2)
        flash_kernel<<<grid, 256, FLASH_SMEM>>>(p_q, p_k, p_v, mask, p_att);
    }

    // 3) output projection (row-major out)
    sgemm2p<0, 0><<<ggrid, 256, P2_SMEM>>>(p_att, wo, bo, nullptr, out);
}